// round 7
// baseline (speedup 1.0000x reference)
#include <cuda_runtime.h>
#include <cuda_bf16.h>
#include <math_constants.h>
#include <cstdint>

// Problem constants
#define NN      20000
#define EE      320000
#define NODE_D  128
#define EDGE_D  16
#define HC      512       // HEADS*EMB
#define HEADS   4
#define EMB     128
#define HIDDEN  512
#define OUTD    64
#define NEG_SLOPE 0.2f

// ---------------- scratch (device globals; no allocation allowed) -------------
__device__ int   g_is64;
__device__ int   g_cnt[NN];
__device__ int   g_off[NN + 1];
__device__ int   g_cur[NN];
__device__ int   g_csr_src[EE];
__device__ int   g_csr_eid[EE];
__device__ float g_loop[NN * EDGE_D];
__device__ float g_Wp[HC * 1024];             // packed+rounded weights (max 512x1024)
__device__ float g_bp[1024];                  // packed bias
__device__ float g_xA[(size_t)NN * NODE_D];   // tf32-rounded copy of x
__device__ float g_xlr[(size_t)NN * 1024];    // [N][1024]: xl | xr (reused as decoder hidden)
__device__ float g_h[(size_t)NN * HC];        // layer outputs (tf32-rounded)

// ---------------- helpers -----------------------------------------------------
__device__ __forceinline__ int edge_val(const void* p, int is64, long long i) {
    return is64 ? (int)((const long long*)p)[i] : ((const int*)p)[i];
}

__device__ __forceinline__ float rna_tf32(float f) {
    unsigned u;
    asm("cvt.rna.tf32.f32 %0, %1;" : "=r"(u) : "f"(f));
    return __uint_as_float(u);
}

// zero counters + detect int64 vs int32 edge_index
__global__ void init_kernel(const void* eidx) {
    int i = blockIdx.x * blockDim.x + threadIdx.x;
    if (i < NN) { g_cnt[i] = 0; g_cur[i] = 0; }
    if (i == 0) {
        const unsigned* p = (const unsigned*)eidx;
        int is64 = 1;
        for (int k = 0; k < 16; k++)
            if (p[2 * k + 1] != 0u) is64 = 0;
        g_is64 = is64;
    }
}

__global__ void count_kernel(const void* eidx) {
    int e = blockIdx.x * blockDim.x + threadIdx.x;
    if (e >= EE) return;
    int is64 = g_is64;
    int dst = edge_val(eidx, is64, (long long)EE + e);
    atomicAdd(&g_cnt[dst], 1);
}

__global__ __launch_bounds__(1024) void scan_kernel() {
    __shared__ int s[1024];
    int tid = threadIdx.x;
    const int per = (NN + 1023) >> 10;
    int start = tid * per;
    int sum = 0;
    for (int i = 0; i < per; i++) {
        int idx = start + i;
        if (idx < NN) sum += g_cnt[idx];
    }
    s[tid] = sum;
    __syncthreads();
    for (int o = 1; o < 1024; o <<= 1) {
        int v = 0;
        if (tid >= o) v = s[tid - o];
        __syncthreads();
        if (tid >= o) s[tid] += v;
        __syncthreads();
    }
    int base = (tid > 0) ? s[tid - 1] : 0;
    for (int i = 0; i < per; i++) {
        int idx = start + i;
        if (idx < NN) { g_off[idx] = base; base += g_cnt[idx]; }
    }
    if (tid == 1023) g_off[NN] = s[1023];
}

__global__ void scatter_kernel(const void* eidx) {
    int e = blockIdx.x * blockDim.x + threadIdx.x;
    if (e >= EE) return;
    int is64 = g_is64;
    int src = edge_val(eidx, is64, e);
    int dst = edge_val(eidx, is64, (long long)EE + e);
    int pos = g_off[dst] + atomicAdd(&g_cur[dst], 1);
    g_csr_src[pos] = src;
    g_csr_eid[pos] = e;
}

// self-loop attr = mean of incoming edge_attr (CSR-based, no atomics)
__global__ __launch_bounds__(128) void loopattr_kernel(const float* __restrict__ ea) {
    int n = blockIdx.x * 4 + (threadIdx.x >> 5);
    if (n >= NN) return;
    int lane = threadIdx.x & 31;
    int beg = g_off[n], end = g_off[n + 1];
    float sum = 0.f;
    if (lane < EDGE_D) {
        for (int i = beg; i < end; i++) {
            int eid = g_csr_eid[i];
            sum += __ldg(&ea[(size_t)eid * EDGE_D + lane]);
        }
        float c = (float)(end - beg);
        g_loop[n * EDGE_D + lane] = sum / fmaxf(c, 1.f);
    }
}

// tf32-round x into g_xA
__global__ void round_x_kernel(const float* __restrict__ x) {
    int i = blockIdx.x * blockDim.x + threadIdx.x;
    if (i < NN * NODE_D) g_xA[i] = rna_tf32(x[i]);
}

// pack [W0|W1] (split at col S) into g_Wp with tf32 rounding; bias into g_bp
__global__ void pack_kernel(const float* __restrict__ W0, const float* __restrict__ W1,
                            const float* __restrict__ b0, const float* __restrict__ b1,
                            int S, int Nn, int K) {
    int i = blockIdx.x * blockDim.x + threadIdx.x;
    if (i < K * Nn) {
        int k = i / Nn, j = i - k * Nn;
        float v = (j < S) ? W0[k * S + j] : W1[k * (Nn - S) + (j - S)];
        g_Wp[i] = rna_tf32(v);
    }
    if (i < Nn) g_bp[i] = (i < S) ? b0[i] : b1[i - S];
}

// ---------------- tf32 tensor-core GEMM (cp.async, 64x64 warp tiles) ----------
// Operands must already be tf32-rounded in memory.
#define BMt 128
#define BNt 128
#define BKt 32
#define AS_STRIDE 36
#define BS_STRIDE 136
#define AS_SIZE (BMt * AS_STRIDE)   // floats
#define BS_SIZE (BKt * BS_STRIDE)
#define GEMM_SMEM ((2 * AS_SIZE + 2 * BS_SIZE) * 4)  // 71680 bytes

__device__ __forceinline__ void cp16(uint32_t dst, const float* src, int sz) {
    asm volatile("cp.async.cg.shared.global [%0], [%1], 16, %2;\n"
                 :: "r"(dst), "l"(src), "r"(sz));
}
__device__ __forceinline__ void cp_commit() {
    asm volatile("cp.async.commit_group;\n" ::: "memory");
}

// A: thread tid loads row tid (8 x 16B). B: thread loads row tid>>2, 32 cols.
__device__ __forceinline__ void load_tiles(
    uint32_t as_u, uint32_t bs_u, const float* aptr, const float* __restrict__ B,
    int kt, int buf, int a_sz, int brow, int colBase, int bcolbase, int Nn)
{
    uint32_t ad = as_u + buf * AS_SIZE * 4;
    const float* ap = aptr + kt;
#pragma unroll
    for (int i = 0; i < 8; i++) cp16(ad + i * 16, ap + i * 4, a_sz);
    uint32_t bd = bs_u + buf * BS_SIZE * 4;
    const float* bp = B + (size_t)(kt + brow) * Nn + colBase + bcolbase;
#pragma unroll
    for (int i = 0; i < 8; i++) {
        int gcol = colBase + bcolbase + i * 4;
        cp16(bd + i * 16, bp + i * 4, (gcol < Nn) ? 16 : 0);
    }
}

__global__ __launch_bounds__(128, 2) void gemm_tc_kernel(
    const float* __restrict__ A, const float* __restrict__ B,
    const float* __restrict__ bias, float* __restrict__ C,
    int M, int Nn, int K, int relu, int round_out)
{
    extern __shared__ float sm[];
    float* As = sm;                    // [2][128][36]
    float* Bs = sm + 2 * AS_SIZE;      // [2][32][136]

    int tid  = threadIdx.x;
    int warp = tid >> 5;
    int lane = tid & 31;
    int gid  = lane >> 2;
    int tg   = lane & 3;

    int warpM = (warp & 1) * 64;       // 2 warps over M
    int warpN = (warp >> 1) * 64;      // 2 warps over N

    int rowBase = blockIdx.y * BMt;
    int colBase = blockIdx.x * BNt;

    float acc[4][8][4];
#pragma unroll
    for (int i = 0; i < 4; i++)
#pragma unroll
        for (int j = 0; j < 8; j++)
#pragma unroll
            for (int r = 0; r < 4; r++) acc[i][j][r] = 0.f;

    // loader indices
    int arow = tid;                      // 0..127 (full row, 8 chunks)
    int brow = tid >> 2;                 // 0..31
    int bcolbase = (tid & 3) * 32;       // 8 chunks of 4 floats
    int agrow = rowBase + arow;
    const float* aptr = A + (size_t)agrow * K;
    int a_sz = (agrow < M) ? 16 : 0;

    uint32_t as_u = (uint32_t)__cvta_generic_to_shared(As) + (arow * AS_STRIDE) * 4;
    uint32_t bs_u = (uint32_t)__cvta_generic_to_shared(Bs) + (brow * BS_STRIDE + bcolbase) * 4;

    load_tiles(as_u, bs_u, aptr, B, 0, 0, a_sz, brow, colBase, bcolbase, Nn);
    cp_commit();

    int nTiles = K / BKt;
    for (int t = 0; t < nTiles; t++) {
        int buf = t & 1;
        if (t + 1 < nTiles) {
            load_tiles(as_u, bs_u, aptr, B, (t + 1) * BKt, buf ^ 1, a_sz, brow, colBase, bcolbase, Nn);
            cp_commit();
            asm volatile("cp.async.wait_group 1;\n" ::: "memory");
        } else {
            asm volatile("cp.async.wait_group 0;\n" ::: "memory");
        }
        __syncthreads();

        const float* Ab = As + buf * AS_SIZE;
        const float* Bb = Bs + buf * BS_SIZE;
#pragma unroll
        for (int ks = 0; ks < 4; ks++) {
            int k0 = ks * 8;
            unsigned af[4][4], bf[8][2];
#pragma unroll
            for (int mt = 0; mt < 4; mt++) {
                int r = warpM + mt * 16;
                af[mt][0] = __float_as_uint(Ab[(r + gid) * AS_STRIDE + k0 + tg]);
                af[mt][1] = __float_as_uint(Ab[(r + gid + 8) * AS_STRIDE + k0 + tg]);
                af[mt][2] = __float_as_uint(Ab[(r + gid) * AS_STRIDE + k0 + tg + 4]);
                af[mt][3] = __float_as_uint(Ab[(r + gid + 8) * AS_STRIDE + k0 + tg + 4]);
            }
#pragma unroll
            for (int nt = 0; nt < 8; nt++) {
                int c = warpN + nt * 8;
                bf[nt][0] = __float_as_uint(Bb[(k0 + tg) * BS_STRIDE + c + gid]);
                bf[nt][1] = __float_as_uint(Bb[(k0 + tg + 4) * BS_STRIDE + c + gid]);
            }
#pragma unroll
            for (int mt = 0; mt < 4; mt++)
#pragma unroll
                for (int nt = 0; nt < 8; nt++) {
                    asm volatile(
                        "mma.sync.aligned.m16n8k8.row.col.f32.tf32.tf32.f32 "
                        "{%0,%1,%2,%3}, {%4,%5,%6,%7}, {%8,%9}, {%0,%1,%2,%3};"
                        : "+f"(acc[mt][nt][0]), "+f"(acc[mt][nt][1]),
                          "+f"(acc[mt][nt][2]), "+f"(acc[mt][nt][3])
                        : "r"(af[mt][0]), "r"(af[mt][1]), "r"(af[mt][2]), "r"(af[mt][3]),
                          "r"(bf[nt][0]), "r"(bf[nt][1]));
                }
        }
        __syncthreads();
    }

    // epilogue
#pragma unroll
    for (int mt = 0; mt < 4; mt++) {
#pragma unroll
        for (int nt = 0; nt < 8; nt++) {
            int r0 = rowBase + warpM + mt * 16 + gid;
            int c0 = colBase + warpN + nt * 8 + tg * 2;
#pragma unroll
            for (int half = 0; half < 2; half++) {
                int row = r0 + half * 8;
                if (row < M) {
#pragma unroll
                    for (int j = 0; j < 2; j++) {
                        int col = c0 + j;
                        if (col < Nn) {
                            float v = acc[mt][nt][half * 2 + j] + bias[col];
                            if (relu) v = fmaxf(v, 0.f);
                            if (round_out) v = rna_tf32(v);
                            C[(size_t)row * Nn + col] = v;
                        }
                    }
                }
            }
        }
    }
}

// ---------------- GATv2 aggregation: persistent blocks, one warp / head -------
__global__ __launch_bounds__(128) void gat_kernel(
    const float* __restrict__ xlr,        // [N][1024] xl|xr
    const float* __restrict__ edge_attr,  // [E][16]
    const float* __restrict__ We,         // [16][512]
    const float* __restrict__ att,        // [512]
    const float* __restrict__ bias,       // [512]
    float* __restrict__ out)              // [N][512] (tf32-rounded: feeds GEMMs only)
{
    __shared__ float We_sh[EDGE_D * HC];
    for (int i = threadIdx.x; i < EDGE_D * HC; i += 128) We_sh[i] = We[i];
    __syncthreads();

    int w = threadIdx.x >> 5;
    int lane = threadIdx.x & 31;
    int cbase = w * EMB + lane;
    const float* Wp = We_sh + cbase;

    float att0 = __ldg(&att[cbase]);
    float att1 = __ldg(&att[cbase + 32]);
    float att2 = __ldg(&att[cbase + 64]);
    float att3 = __ldg(&att[cbase + 96]);
    float b0v = __ldg(&bias[cbase]);
    float b1v = __ldg(&bias[cbase + 32]);
    float b2v = __ldg(&bias[cbase + 64]);
    float b3v = __ldg(&bias[cbase + 96]);

#define LOAD_EDGE(IDX, N_, END_, SRC, EAV) do {                              \
        const float* _ea;                                                    \
        if ((IDX) < (END_)) {                                                \
            SRC = __ldg(&g_csr_src[IDX]);                                    \
            _ea = edge_attr + (size_t)__ldg(&g_csr_eid[IDX]) * EDGE_D;       \
        } else {                                                             \
            SRC = (N_);                                                      \
            _ea = g_loop + (size_t)(N_) * EDGE_D;                            \
        }                                                                    \
        EAV = (lane < EDGE_D) ? __ldg(&_ea[lane]) : 0.f;                     \
    } while (0)

#define LOAD_X(SRC, X0, X1, X2, X3) do {                                     \
        const float* _xp = xlr + (size_t)(SRC) * 1024 + cbase;               \
        X0 = __ldg(&_xp[0]);  X1 = __ldg(&_xp[32]);                          \
        X2 = __ldg(&_xp[64]); X3 = __ldg(&_xp[96]);                          \
    } while (0)

    for (int n = blockIdx.x; n < NN; n += gridDim.x) {
        const float* xrp = xlr + (size_t)n * 1024 + HC + cbase;
        float xr0 = xrp[0], xr1 = xrp[32], xr2 = xrp[64], xr3 = xrp[96];

        float m = -CUDART_INF_F, den = 0.f;
        float a0 = 0.f, a1 = 0.f, a2 = 0.f, a3 = 0.f;

        int beg = g_off[n], end = g_off[n + 1];

        int src; float eav;
        float x0, x1, x2, x3;
        LOAD_EDGE(beg, n, end, src, eav);
        LOAD_X(src, x0, x1, x2, x3);

        for (int idx = beg; idx <= end; idx++) {
            float cx0 = x0, cx1 = x1, cx2 = x2, cx3 = x3;
            float ce = eav;

            if (idx < end) {                    // prefetch next edge
                LOAD_EDGE(idx + 1, n, end, src, eav);
                LOAD_X(src, x0, x1, x2, x3);
            }

            float e0 = xr0, e1 = xr1, e2 = xr2, e3 = xr3;
#pragma unroll
            for (int d = 0; d < EDGE_D; d++) {
                float av = __shfl_sync(0xffffffffu, ce, d);
                e0 = fmaf(av, Wp[d * HC], e0);
                e1 = fmaf(av, Wp[d * HC + 32], e1);
                e2 = fmaf(av, Wp[d * HC + 64], e2);
                e3 = fmaf(av, Wp[d * HC + 96], e3);
            }
            float s0 = cx0 + e0, s1 = cx1 + e1, s2 = cx2 + e2, s3 = cx3 + e3;
            float l0 = fmaxf(s0, NEG_SLOPE * s0);
            float l1 = fmaxf(s1, NEG_SLOPE * s1);
            float l2 = fmaxf(s2, NEG_SLOPE * s2);
            float l3 = fmaxf(s3, NEG_SLOPE * s3);

            float p = l0 * att0;
            p = fmaf(l1, att1, p);
            p = fmaf(l2, att2, p);
            p = fmaf(l3, att3, p);
#pragma unroll
            for (int o = 16; o > 0; o >>= 1) p += __shfl_xor_sync(0xffffffffu, p, o);

            float nm = fmaxf(m, p);
            float corr = __expf(m - nm);
            float pe   = __expf(p - nm);
            den = den * corr + pe;
            a0 = a0 * corr + pe * cx0;
            a1 = a1 * corr + pe * cx1;
            a2 = a2 * corr + pe * cx2;
            a3 = a3 * corr + pe * cx3;
            m = nm;
        }
        float inv = 1.f / (den + 1e-16f);
        float* op = out + (size_t)n * HC + cbase;
        op[0]  = rna_tf32(fmaf(a0, inv, b0v));
        op[32] = rna_tf32(fmaf(a1, inv, b1v));
        op[64] = rna_tf32(fmaf(a2, inv, b2v));
        op[96] = rna_tf32(fmaf(a3, inv, b3v));
    }
#undef LOAD_EDGE
#undef LOAD_X
}

// ---------------- launch ------------------------------------------------------
extern "C" void kernel_launch(void* const* d_in, const int* in_sizes, int n_in,
                              void* d_out, int out_size) {
    const float* x     = (const float*)d_in[0];
    const void*  eidx  = d_in[1];
    const float* eattr = (const float*)d_in[2];
    const float* Wl1   = (const float*)d_in[3];
    const float* bl1   = (const float*)d_in[4];
    const float* Wr1   = (const float*)d_in[5];
    const float* br1   = (const float*)d_in[6];
    const float* We1   = (const float*)d_in[7];
    const float* att1  = (const float*)d_in[8];
    const float* bias1 = (const float*)d_in[9];
    const float* Wl2   = (const float*)d_in[10];
    const float* bl2   = (const float*)d_in[11];
    const float* Wr2   = (const float*)d_in[12];
    const float* br2   = (const float*)d_in[13];
    const float* We2   = (const float*)d_in[14];
    const float* att2  = (const float*)d_in[15];
    const float* bias2 = (const float*)d_in[16];
    const float* Wd1   = (const float*)d_in[17];
    const float* bd1   = (const float*)d_in[18];
    const float* Wd2   = (const float*)d_in[19];
    const float* bd2   = (const float*)d_in[20];
    float* out = (float*)d_out;

    float* xlr; cudaGetSymbolAddress((void**)&xlr, g_xlr);
    float* h;   cudaGetSymbolAddress((void**)&h, g_h);
    float* xA;  cudaGetSymbolAddress((void**)&xA, g_xA);
    float* Wp;  cudaGetSymbolAddress((void**)&Wp, g_Wp);
    float* bp;  cudaGetSymbolAddress((void**)&bp, g_bp);

    cudaFuncSetAttribute(gemm_tc_kernel,
                         cudaFuncAttributeMaxDynamicSharedMemorySize, GEMM_SMEM);

    dim3 blk(128);
    dim3 grid_lr(1024 / BNt, (NN + BMt - 1) / BMt);
    dim3 grid_d1((HIDDEN + BNt - 1) / BNt, (NN + BMt - 1) / BMt);
    dim3 grid_d2((OUTD + BNt - 1) / BNt, (NN + BMt - 1) / BMt);

    // ---- layer-1 GEMM first (4th launch -> ncu capture lands here) ----
    init_kernel<<<(NN + 255) / 256, 256>>>(eidx);
    round_x_kernel<<<(NN * NODE_D + 255) / 256, 256>>>(x);
    pack_kernel<<<(NODE_D * 1024 + 255) / 256, 256>>>(Wl1, Wr1, bl1, br1, HC, 1024, NODE_D);
    gemm_tc_kernel<<<grid_lr, blk, GEMM_SMEM>>>(xA, Wp, bp, xlr, NN, 1024, NODE_D, 0, 0);

    // ---- CSR preprocessing ----
    count_kernel<<<(EE + 255) / 256, 256>>>(eidx);
    scan_kernel<<<1, 1024>>>();
    scatter_kernel<<<(EE + 255) / 256, 256>>>(eidx);
    loopattr_kernel<<<(NN + 3) / 4, 128>>>(eattr);

    // ---- layer 1 aggregation ----
    gat_kernel<<<2048, 128>>>(xlr, eattr, We1, att1, bias1, h);

    // ---- layer 2 ----
    pack_kernel<<<(HC * 1024 + 255) / 256, 256>>>(Wl2, Wr2, bl2, br2, HC, 1024, HC);
    gemm_tc_kernel<<<grid_lr, blk, GEMM_SMEM>>>(h, Wp, bp, xlr, NN, 1024, HC, 0, 0);
    gat_kernel<<<2048, 128>>>(xlr, eattr, We2, att2, bias2, h);

    // ---- decoder ----
    float* hid = xlr;  // reuse scratch
    pack_kernel<<<(HC * HIDDEN + 255) / 256, 256>>>(Wd1, Wd1, bd1, bd1, HIDDEN, HIDDEN, HC);
    gemm_tc_kernel<<<grid_d1, blk, GEMM_SMEM>>>(h, Wp, bp, hid, NN, HIDDEN, HC, 1, 1);
    pack_kernel<<<(HIDDEN * OUTD + 255) / 256, 256>>>(Wd2, Wd2, bd2, bd2, OUTD, OUTD, HIDDEN);
    gemm_tc_kernel<<<grid_d2, blk, GEMM_SMEM>>>(hid, Wp, bp, out, NN, OUTD, HIDDEN, 0, 0);
}

// round 8
// speedup vs baseline: 1.0664x; 1.0664x over previous
#include <cuda_runtime.h>
#include <cuda_bf16.h>
#include <math_constants.h>
#include <cstdint>

// Problem constants
#define NN      20000
#define EE      320000
#define NODE_D  128
#define EDGE_D  16
#define HC      512       // HEADS*EMB
#define HEADS   4
#define EMB     128
#define HIDDEN  512
#define OUTD    64
#define NEG_SLOPE 0.2f

// ---------------- scratch (device globals; no allocation allowed) -------------
__device__ int   g_is64;
__device__ int   g_cnt[NN];
__device__ int   g_off[NN + 1];
__device__ int   g_cur[NN];
__device__ int   g_csr_src[EE];
__device__ int   g_csr_eid[EE];
__device__ float g_loop[NN * EDGE_D];
__device__ float g_Wp[HC * 1024];             // packed+rounded weights (max 512x1024)
__device__ float g_bp[1024];                  // packed bias
__device__ float g_xA[(size_t)NN * NODE_D];   // tf32-rounded copy of x
__device__ float g_xlr[(size_t)NN * 1024];    // [N][1024]: xl | xr (reused as decoder hidden)
__device__ float g_h[(size_t)NN * HC];        // layer outputs (tf32-rounded)

// ---------------- helpers -----------------------------------------------------
__device__ __forceinline__ int edge_val(const void* p, int is64, long long i) {
    return is64 ? (int)((const long long*)p)[i] : ((const int*)p)[i];
}

__device__ __forceinline__ float rna_tf32(float f) {
    unsigned u;
    asm("cvt.rna.tf32.f32 %0, %1;" : "=r"(u) : "f"(f));
    return __uint_as_float(u);
}

// zero counters + detect int64 vs int32 edge_index
__global__ void init_kernel(const void* eidx) {
    int i = blockIdx.x * blockDim.x + threadIdx.x;
    if (i < NN) { g_cnt[i] = 0; g_cur[i] = 0; }
    if (i == 0) {
        const unsigned* p = (const unsigned*)eidx;
        int is64 = 1;
        for (int k = 0; k < 16; k++)
            if (p[2 * k + 1] != 0u) is64 = 0;
        g_is64 = is64;
    }
}

__global__ void count_kernel(const void* eidx) {
    int e = blockIdx.x * blockDim.x + threadIdx.x;
    if (e >= EE) return;
    int is64 = g_is64;
    int dst = edge_val(eidx, is64, (long long)EE + e);
    atomicAdd(&g_cnt[dst], 1);
}

__global__ __launch_bounds__(1024) void scan_kernel() {
    __shared__ int s[1024];
    int tid = threadIdx.x;
    const int per = (NN + 1023) >> 10;
    int start = tid * per;
    int sum = 0;
    for (int i = 0; i < per; i++) {
        int idx = start + i;
        if (idx < NN) sum += g_cnt[idx];
    }
    s[tid] = sum;
    __syncthreads();
    for (int o = 1; o < 1024; o <<= 1) {
        int v = 0;
        if (tid >= o) v = s[tid - o];
        __syncthreads();
        if (tid >= o) s[tid] += v;
        __syncthreads();
    }
    int base = (tid > 0) ? s[tid - 1] : 0;
    for (int i = 0; i < per; i++) {
        int idx = start + i;
        if (idx < NN) { g_off[idx] = base; base += g_cnt[idx]; }
    }
    if (tid == 1023) g_off[NN] = s[1023];
}

__global__ void scatter_kernel(const void* eidx) {
    int e = blockIdx.x * blockDim.x + threadIdx.x;
    if (e >= EE) return;
    int is64 = g_is64;
    int src = edge_val(eidx, is64, e);
    int dst = edge_val(eidx, is64, (long long)EE + e);
    int pos = g_off[dst] + atomicAdd(&g_cur[dst], 1);
    g_csr_src[pos] = src;
    g_csr_eid[pos] = e;
}

// self-loop attr = mean of incoming edge_attr (CSR-based, no atomics)
__global__ __launch_bounds__(128) void loopattr_kernel(const float* __restrict__ ea) {
    int n = blockIdx.x * 4 + (threadIdx.x >> 5);
    if (n >= NN) return;
    int lane = threadIdx.x & 31;
    int beg = g_off[n], end = g_off[n + 1];
    float sum = 0.f;
    if (lane < EDGE_D) {
        for (int i = beg; i < end; i++) {
            int eid = g_csr_eid[i];
            sum += __ldg(&ea[(size_t)eid * EDGE_D + lane]);
        }
        float c = (float)(end - beg);
        g_loop[n * EDGE_D + lane] = sum / fmaxf(c, 1.f);
    }
}

// tf32-round x into g_xA
__global__ void round_x_kernel(const float* __restrict__ x) {
    int i = blockIdx.x * blockDim.x + threadIdx.x;
    if (i < NN * NODE_D) g_xA[i] = rna_tf32(x[i]);
}

// pack [W0|W1] (split at col S) into g_Wp with tf32 rounding; bias into g_bp
__global__ void pack_kernel(const float* __restrict__ W0, const float* __restrict__ W1,
                            const float* __restrict__ b0, const float* __restrict__ b1,
                            int S, int Nn, int K) {
    int i = blockIdx.x * blockDim.x + threadIdx.x;
    if (i < K * Nn) {
        int k = i / Nn, j = i - k * Nn;
        float v = (j < S) ? W0[k * S + j] : W1[k * (Nn - S) + (j - S)];
        g_Wp[i] = rna_tf32(v);
    }
    if (i < Nn) g_bp[i] = (i < S) ? b0[i] : b1[i - S];
}

// ---------------- tf32 tensor-core GEMM (cp.async, 64x64 warp tiles) ----------
// Operands must already be tf32-rounded in memory.
#define BMt 128
#define BNt 128
#define BKt 32
#define AS_STRIDE 36
#define BS_STRIDE 136
#define AS_SIZE (BMt * AS_STRIDE)   // floats
#define BS_SIZE (BKt * BS_STRIDE)
#define GEMM_SMEM ((2 * AS_SIZE + 2 * BS_SIZE) * 4)  // 71680 bytes

__device__ __forceinline__ void cp16(uint32_t dst, const float* src, int sz) {
    asm volatile("cp.async.cg.shared.global [%0], [%1], 16, %2;\n"
                 :: "r"(dst), "l"(src), "r"(sz));
}
__device__ __forceinline__ void cp_commit() {
    asm volatile("cp.async.commit_group;\n" ::: "memory");
}

// A: thread tid loads row tid (8 x 16B). B: thread loads row tid>>2, 32 cols.
__device__ __forceinline__ void load_tiles(
    uint32_t as_u, uint32_t bs_u, const float* aptr, const float* __restrict__ B,
    int kt, int buf, int a_sz, int brow, int colBase, int bcolbase, int Nn)
{
    uint32_t ad = as_u + buf * AS_SIZE * 4;
    const float* ap = aptr + kt;
#pragma unroll
    for (int i = 0; i < 8; i++) cp16(ad + i * 16, ap + i * 4, a_sz);
    uint32_t bd = bs_u + buf * BS_SIZE * 4;
    const float* bp = B + (size_t)(kt + brow) * Nn + colBase + bcolbase;
#pragma unroll
    for (int i = 0; i < 8; i++) {
        int gcol = colBase + bcolbase + i * 4;
        cp16(bd + i * 16, bp + i * 4, (gcol < Nn) ? 16 : 0);
    }
}

__global__ __launch_bounds__(128, 3) void gemm_tc_kernel(
    const float* __restrict__ A, const float* __restrict__ B,
    const float* __restrict__ bias, float* __restrict__ C,
    int M, int Nn, int K, int relu, int round_out)
{
    extern __shared__ float sm[];
    float* As = sm;                    // [2][128][36]
    float* Bs = sm + 2 * AS_SIZE;      // [2][32][136]

    int tid  = threadIdx.x;
    int warp = tid >> 5;
    int lane = tid & 31;
    int gid  = lane >> 2;
    int tg   = lane & 3;

    int warpM = (warp & 1) * 64;       // 2 warps over M
    int warpN = (warp >> 1) * 64;      // 2 warps over N

    int rowBase = blockIdx.y * BMt;
    int colBase = blockIdx.x * BNt;

    float acc[4][8][4];
#pragma unroll
    for (int i = 0; i < 4; i++)
#pragma unroll
        for (int j = 0; j < 8; j++)
#pragma unroll
            for (int r = 0; r < 4; r++) acc[i][j][r] = 0.f;

    // loader indices
    int arow = tid;                      // 0..127 (full row, 8 chunks)
    int brow = tid >> 2;                 // 0..31
    int bcolbase = (tid & 3) * 32;       // 8 chunks of 4 floats
    int agrow = rowBase + arow;
    const float* aptr = A + (size_t)agrow * K;
    int a_sz = (agrow < M) ? 16 : 0;

    uint32_t as_u = (uint32_t)__cvta_generic_to_shared(As) + (arow * AS_STRIDE) * 4;
    uint32_t bs_u = (uint32_t)__cvta_generic_to_shared(Bs) + (brow * BS_STRIDE + bcolbase) * 4;

    load_tiles(as_u, bs_u, aptr, B, 0, 0, a_sz, brow, colBase, bcolbase, Nn);
    cp_commit();

    int nTiles = K / BKt;
    for (int t = 0; t < nTiles; t++) {
        int buf = t & 1;
        if (t + 1 < nTiles) {
            load_tiles(as_u, bs_u, aptr, B, (t + 1) * BKt, buf ^ 1, a_sz, brow, colBase, bcolbase, Nn);
            cp_commit();
            asm volatile("cp.async.wait_group 1;\n" ::: "memory");
        } else {
            asm volatile("cp.async.wait_group 0;\n" ::: "memory");
        }
        __syncthreads();

        const float* Ab = As + buf * AS_SIZE;
        const float* Bb = Bs + buf * BS_SIZE;
#pragma unroll
        for (int ks = 0; ks < 4; ks++) {
            int k0 = ks * 8;
            unsigned af[4][4], bf[8][2];
#pragma unroll
            for (int mt = 0; mt < 4; mt++) {
                int r = warpM + mt * 16;
                af[mt][0] = __float_as_uint(Ab[(r + gid) * AS_STRIDE + k0 + tg]);
                af[mt][1] = __float_as_uint(Ab[(r + gid + 8) * AS_STRIDE + k0 + tg]);
                af[mt][2] = __float_as_uint(Ab[(r + gid) * AS_STRIDE + k0 + tg + 4]);
                af[mt][3] = __float_as_uint(Ab[(r + gid + 8) * AS_STRIDE + k0 + tg + 4]);
            }
#pragma unroll
            for (int nt = 0; nt < 8; nt++) {
                int c = warpN + nt * 8;
                bf[nt][0] = __float_as_uint(Bb[(k0 + tg) * BS_STRIDE + c + gid]);
                bf[nt][1] = __float_as_uint(Bb[(k0 + tg + 4) * BS_STRIDE + c + gid]);
            }
#pragma unroll
            for (int mt = 0; mt < 4; mt++)
#pragma unroll
                for (int nt = 0; nt < 8; nt++) {
                    asm volatile(
                        "mma.sync.aligned.m16n8k8.row.col.f32.tf32.tf32.f32 "
                        "{%0,%1,%2,%3}, {%4,%5,%6,%7}, {%8,%9}, {%0,%1,%2,%3};"
                        : "+f"(acc[mt][nt][0]), "+f"(acc[mt][nt][1]),
                          "+f"(acc[mt][nt][2]), "+f"(acc[mt][nt][3])
                        : "r"(af[mt][0]), "r"(af[mt][1]), "r"(af[mt][2]), "r"(af[mt][3]),
                          "r"(bf[nt][0]), "r"(bf[nt][1]));
                }
        }
        __syncthreads();
    }

    // epilogue
#pragma unroll
    for (int mt = 0; mt < 4; mt++) {
#pragma unroll
        for (int nt = 0; nt < 8; nt++) {
            int r0 = rowBase + warpM + mt * 16 + gid;
            int c0 = colBase + warpN + nt * 8 + tg * 2;
#pragma unroll
            for (int half = 0; half < 2; half++) {
                int row = r0 + half * 8;
                if (row < M) {
#pragma unroll
                    for (int j = 0; j < 2; j++) {
                        int col = c0 + j;
                        if (col < Nn) {
                            float v = acc[mt][nt][half * 2 + j] + bias[col];
                            if (relu) v = fmaxf(v, 0.f);
                            if (round_out) v = rna_tf32(v);
                            C[(size_t)row * Nn + col] = v;
                        }
                    }
                }
            }
        }
    }
}

// ---------------- GATv2 aggregation: one block / node, one warp / head --------
__global__ __launch_bounds__(128) void gat_kernel(
    const float* __restrict__ xlr,        // [N][1024] xl|xr
    const float* __restrict__ edge_attr,  // [E][16]
    const float* __restrict__ We,         // [16][512]
    const float* __restrict__ att,        // [512]
    const float* __restrict__ bias,       // [512]
    float* __restrict__ out)              // [N][512] (tf32-rounded: feeds GEMMs only)
{
    __shared__ float We_sh[EDGE_D * HC];
    for (int i = threadIdx.x; i < EDGE_D * HC; i += 128) We_sh[i] = We[i];
    __syncthreads();

    int w = threadIdx.x >> 5;
    int lane = threadIdx.x & 31;
    int cbase = w * EMB + lane;
    const float* Wp = We_sh + cbase;

    float att0 = __ldg(&att[cbase]);
    float att1 = __ldg(&att[cbase + 32]);
    float att2 = __ldg(&att[cbase + 64]);
    float att3 = __ldg(&att[cbase + 96]);

    int n = blockIdx.x;

    const float* xrp = xlr + (size_t)n * 1024 + HC + cbase;
    float xr0 = xrp[0], xr1 = xrp[32], xr2 = xrp[64], xr3 = xrp[96];

    float m = -CUDART_INF_F, den = 0.f;
    float a0 = 0.f, a1 = 0.f, a2 = 0.f, a3 = 0.f;

    int beg = g_off[n], end = g_off[n + 1];

#define LOAD_EDGE(IDX, SRC, EAV) do {                                        \
        const float* _ea;                                                    \
        if ((IDX) < end) {                                                   \
            SRC = __ldg(&g_csr_src[IDX]);                                    \
            _ea = edge_attr + (size_t)__ldg(&g_csr_eid[IDX]) * EDGE_D;       \
        } else {                                                             \
            SRC = n;                                                         \
            _ea = g_loop + (size_t)n * EDGE_D;                               \
        }                                                                    \
        EAV = (lane < EDGE_D) ? __ldg(&_ea[lane]) : 0.f;                     \
    } while (0)

#define LOAD_X(SRC, X0, X1, X2, X3) do {                                     \
        const float* _xp = xlr + (size_t)(SRC) * 1024 + cbase;               \
        X0 = __ldg(&_xp[0]);  X1 = __ldg(&_xp[32]);                          \
        X2 = __ldg(&_xp[64]); X3 = __ldg(&_xp[96]);                          \
    } while (0)

    int src; float eav;
    float x0, x1, x2, x3;
    LOAD_EDGE(beg, src, eav);
    LOAD_X(src, x0, x1, x2, x3);

    for (int idx = beg; idx <= end; idx++) {
        float cx0 = x0, cx1 = x1, cx2 = x2, cx3 = x3;
        float ce = eav;

        if (idx < end) {                    // prefetch next edge
            LOAD_EDGE(idx + 1, src, eav);
            LOAD_X(src, x0, x1, x2, x3);
        }

        float e0 = xr0, e1 = xr1, e2 = xr2, e3 = xr3;
#pragma unroll
        for (int d = 0; d < EDGE_D; d++) {
            float av = __shfl_sync(0xffffffffu, ce, d);
            e0 = fmaf(av, Wp[d * HC], e0);
            e1 = fmaf(av, Wp[d * HC + 32], e1);
            e2 = fmaf(av, Wp[d * HC + 64], e2);
            e3 = fmaf(av, Wp[d * HC + 96], e3);
        }
        float s0 = cx0 + e0, s1 = cx1 + e1, s2 = cx2 + e2, s3 = cx3 + e3;
        float l0 = fmaxf(s0, NEG_SLOPE * s0);
        float l1 = fmaxf(s1, NEG_SLOPE * s1);
        float l2 = fmaxf(s2, NEG_SLOPE * s2);
        float l3 = fmaxf(s3, NEG_SLOPE * s3);

        float p = l0 * att0;
        p = fmaf(l1, att1, p);
        p = fmaf(l2, att2, p);
        p = fmaf(l3, att3, p);
#pragma unroll
        for (int o = 16; o > 0; o >>= 1) p += __shfl_xor_sync(0xffffffffu, p, o);

        float nm = fmaxf(m, p);
        float corr = __expf(m - nm);
        float pe   = __expf(p - nm);
        den = den * corr + pe;
        a0 = a0 * corr + pe * cx0;
        a1 = a1 * corr + pe * cx1;
        a2 = a2 * corr + pe * cx2;
        a3 = a3 * corr + pe * cx3;
        m = nm;
    }
    float inv = 1.f / (den + 1e-16f);
    float* op = out + (size_t)n * HC + cbase;
    op[0]  = rna_tf32(fmaf(a0, inv, __ldg(&bias[cbase])));
    op[32] = rna_tf32(fmaf(a1, inv, __ldg(&bias[cbase + 32])));
    op[64] = rna_tf32(fmaf(a2, inv, __ldg(&bias[cbase + 64])));
    op[96] = rna_tf32(fmaf(a3, inv, __ldg(&bias[cbase + 96])));
#undef LOAD_EDGE
#undef LOAD_X
}

// ---------------- launch ------------------------------------------------------
extern "C" void kernel_launch(void* const* d_in, const int* in_sizes, int n_in,
                              void* d_out, int out_size) {
    const float* x     = (const float*)d_in[0];
    const void*  eidx  = d_in[1];
    const float* eattr = (const float*)d_in[2];
    const float* Wl1   = (const float*)d_in[3];
    const float* bl1   = (const float*)d_in[4];
    const float* Wr1   = (const float*)d_in[5];
    const float* br1   = (const float*)d_in[6];
    const float* We1   = (const float*)d_in[7];
    const float* att1  = (const float*)d_in[8];
    const float* bias1 = (const float*)d_in[9];
    const float* Wl2   = (const float*)d_in[10];
    const float* bl2   = (const float*)d_in[11];
    const float* Wr2   = (const float*)d_in[12];
    const float* br2   = (const float*)d_in[13];
    const float* We2   = (const float*)d_in[14];
    const float* att2  = (const float*)d_in[15];
    const float* bias2 = (const float*)d_in[16];
    const float* Wd1   = (const float*)d_in[17];
    const float* bd1   = (const float*)d_in[18];
    const float* Wd2   = (const float*)d_in[19];
    const float* bd2   = (const float*)d_in[20];
    float* out = (float*)d_out;

    float* xlr; cudaGetSymbolAddress((void**)&xlr, g_xlr);
    float* h;   cudaGetSymbolAddress((void**)&h, g_h);
    float* xA;  cudaGetSymbolAddress((void**)&xA, g_xA);
    float* Wp;  cudaGetSymbolAddress((void**)&Wp, g_Wp);
    float* bp;  cudaGetSymbolAddress((void**)&bp, g_bp);

    cudaFuncSetAttribute(gemm_tc_kernel,
                         cudaFuncAttributeMaxDynamicSharedMemorySize, GEMM_SMEM);

    dim3 blk(128);
    dim3 grid_lr(1024 / BNt, (NN + BMt - 1) / BMt);
    dim3 grid_d1((HIDDEN + BNt - 1) / BNt, (NN + BMt - 1) / BMt);
    dim3 grid_d2((OUTD + BNt - 1) / BNt, (NN + BMt - 1) / BMt);

    // ---- layer-1 GEMM first (4th launch -> ncu capture lands here) ----
    init_kernel<<<(NN + 255) / 256, 256>>>(eidx);
    round_x_kernel<<<(NN * NODE_D + 255) / 256, 256>>>(x);
    pack_kernel<<<(NODE_D * 1024 + 255) / 256, 256>>>(Wl1, Wr1, bl1, br1, HC, 1024, NODE_D);
    gemm_tc_kernel<<<grid_lr, blk, GEMM_SMEM>>>(xA, Wp, bp, xlr, NN, 1024, NODE_D, 0, 0);

    // ---- CSR preprocessing ----
    count_kernel<<<(EE + 255) / 256, 256>>>(eidx);
    scan_kernel<<<1, 1024>>>();
    scatter_kernel<<<(EE + 255) / 256, 256>>>(eidx);
    loopattr_kernel<<<(NN + 3) / 4, 128>>>(eattr);

    // ---- layer 1 aggregation ----
    gat_kernel<<<NN, 128>>>(xlr, eattr, We1, att1, bias1, h);

    // ---- layer 2 ----
    pack_kernel<<<(HC * 1024 + 255) / 256, 256>>>(Wl2, Wr2, bl2, br2, HC, 1024, HC);
    gemm_tc_kernel<<<grid_lr, blk, GEMM_SMEM>>>(h, Wp, bp, xlr, NN, 1024, HC, 0, 0);
    gat_kernel<<<NN, 128>>>(xlr, eattr, We2, att2, bias2, h);

    // ---- decoder ----
    float* hid = xlr;  // reuse scratch
    pack_kernel<<<(HC * HIDDEN + 255) / 256, 256>>>(Wd1, Wd1, bd1, bd1, HIDDEN, HIDDEN, HC);
    gemm_tc_kernel<<<grid_d1, blk, GEMM_SMEM>>>(h, Wp, bp, hid, NN, HIDDEN, HC, 1, 1);
    pack_kernel<<<(HIDDEN * OUTD + 255) / 256, 256>>>(Wd2, Wd2, bd2, bd2, OUTD, OUTD, HIDDEN);
    gemm_tc_kernel<<<grid_d2, blk, GEMM_SMEM>>>(hid, Wp, bp, out, NN, OUTD, HIDDEN, 0, 0);
}

// round 9
// speedup vs baseline: 1.1151x; 1.0457x over previous
#include <cuda_runtime.h>
#include <cuda_bf16.h>
#include <math_constants.h>
#include <cstdint>

// Problem constants
#define NN      20000
#define EE      320000
#define NODE_D  128
#define EDGE_D  16
#define HC      512       // HEADS*EMB
#define HEADS   4
#define EMB     128
#define HIDDEN  512
#define OUTD    64
#define NEG_SLOPE 0.2f

// ---------------- scratch (device globals; no allocation allowed) -------------
__device__ int   g_is64;
__device__ int   g_cnt[NN];
__device__ int   g_off[NN + 1];
__device__ int   g_cur[NN];
__device__ int   g_csr_src[EE];
__device__ int   g_csr_eid[EE];
__device__ float g_loop[NN * EDGE_D];
__device__ float g_Wp[HC * 1024];             // packed+rounded weights (max 512x1024)
__device__ float g_bp[1024];                  // packed bias
__device__ float g_xA[(size_t)NN * NODE_D];   // tf32-rounded copy of x
__device__ float g_xlr[(size_t)NN * 1024];    // [N][1024]: xl | xr (reused as decoder hidden)
__device__ float g_h[(size_t)NN * HC];        // layer outputs (tf32-rounded)

// ---------------- helpers -----------------------------------------------------
__device__ __forceinline__ int edge_val(const void* p, int is64, long long i) {
    return is64 ? (int)((const long long*)p)[i] : ((const int*)p)[i];
}

__device__ __forceinline__ float rna_tf32(float f) {
    unsigned u;
    asm("cvt.rna.tf32.f32 %0, %1;" : "=r"(u) : "f"(f));
    return __uint_as_float(u);
}

// zero counters + detect int64 vs int32 edge_index
__global__ void init_kernel(const void* eidx) {
    int i = blockIdx.x * blockDim.x + threadIdx.x;
    if (i < NN) { g_cnt[i] = 0; g_cur[i] = 0; }
    if (i == 0) {
        const unsigned* p = (const unsigned*)eidx;
        int is64 = 1;
        for (int k = 0; k < 16; k++)
            if (p[2 * k + 1] != 0u) is64 = 0;
        g_is64 = is64;
    }
}

__global__ void count_kernel(const void* eidx) {
    int e = blockIdx.x * blockDim.x + threadIdx.x;
    if (e >= EE) return;
    int is64 = g_is64;
    int dst = edge_val(eidx, is64, (long long)EE + e);
    atomicAdd(&g_cnt[dst], 1);
}

__global__ __launch_bounds__(1024) void scan_kernel() {
    __shared__ int s[1024];
    int tid = threadIdx.x;
    const int per = (NN + 1023) >> 10;
    int start = tid * per;
    int sum = 0;
    for (int i = 0; i < per; i++) {
        int idx = start + i;
        if (idx < NN) sum += g_cnt[idx];
    }
    s[tid] = sum;
    __syncthreads();
    for (int o = 1; o < 1024; o <<= 1) {
        int v = 0;
        if (tid >= o) v = s[tid - o];
        __syncthreads();
        if (tid >= o) s[tid] += v;
        __syncthreads();
    }
    int base = (tid > 0) ? s[tid - 1] : 0;
    for (int i = 0; i < per; i++) {
        int idx = start + i;
        if (idx < NN) { g_off[idx] = base; base += g_cnt[idx]; }
    }
    if (tid == 1023) g_off[NN] = s[1023];
}

__global__ void scatter_kernel(const void* eidx) {
    int e = blockIdx.x * blockDim.x + threadIdx.x;
    if (e >= EE) return;
    int is64 = g_is64;
    int src = edge_val(eidx, is64, e);
    int dst = edge_val(eidx, is64, (long long)EE + e);
    int pos = g_off[dst] + atomicAdd(&g_cur[dst], 1);
    g_csr_src[pos] = src;
    g_csr_eid[pos] = e;
}

// self-loop attr = mean of incoming edge_attr (CSR-based, no atomics)
__global__ __launch_bounds__(128) void loopattr_kernel(const float* __restrict__ ea) {
    int n = blockIdx.x * 4 + (threadIdx.x >> 5);
    if (n >= NN) return;
    int lane = threadIdx.x & 31;
    int beg = g_off[n], end = g_off[n + 1];
    float sum = 0.f;
    if (lane < EDGE_D) {
        for (int i = beg; i < end; i++) {
            int eid = g_csr_eid[i];
            sum += __ldg(&ea[(size_t)eid * EDGE_D + lane]);
        }
        float c = (float)(end - beg);
        g_loop[n * EDGE_D + lane] = sum / fmaxf(c, 1.f);
    }
}

// tf32-round x into g_xA
__global__ void round_x_kernel(const float* __restrict__ x) {
    int i = blockIdx.x * blockDim.x + threadIdx.x;
    if (i < NN * NODE_D) g_xA[i] = rna_tf32(x[i]);
}

// pack [W0|W1] (split at col S) into g_Wp with tf32 rounding; bias into g_bp
__global__ void pack_kernel(const float* __restrict__ W0, const float* __restrict__ W1,
                            const float* __restrict__ b0, const float* __restrict__ b1,
                            int S, int Nn, int K) {
    int i = blockIdx.x * blockDim.x + threadIdx.x;
    if (i < K * Nn) {
        int k = i / Nn, j = i - k * Nn;
        float v = (j < S) ? W0[k * S + j] : W1[k * (Nn - S) + (j - S)];
        g_Wp[i] = rna_tf32(v);
    }
    if (i < Nn) g_bp[i] = (i < S) ? b0[i] : b1[i - S];
}

// ---------------- tf32 tensor-core GEMM (3-stage cp.async pipeline) -----------
// Operands must already be tf32-rounded in memory. 256 threads, 64x32 warp tile.
#define BMt 128
#define BNt 128
#define BKt 32
#define AS_STRIDE 36
#define BS_STRIDE 136
#define AS_SIZE (BMt * AS_STRIDE)            // floats
#define BS_SIZE (BKt * BS_STRIDE)
#define STAGE_FLOATS (AS_SIZE + BS_SIZE)     // 8960 floats = 35840 B
#define GEMM_SMEM (3 * STAGE_FLOATS * 4)     // 107520 B

__device__ __forceinline__ void cp16(uint32_t dst, const float* src, int sz) {
    asm volatile("cp.async.cg.shared.global [%0], [%1], 16, %2;\n"
                 :: "r"(dst), "l"(src), "r"(sz));
}
__device__ __forceinline__ void cp_commit() {
    asm volatile("cp.async.commit_group;\n" ::: "memory");
}

// 256 threads. A: thread loads row tid>>1, 16-float half (4 x 16B).
// B: thread loads row tid>>3, 16-float chunk (4 x 16B).
__device__ __forceinline__ void load_tiles(
    uint32_t as_u, uint32_t bs_u, const float* aptr, const float* __restrict__ B,
    int kt, int buf, int a_sz, int brow, int colBase, int bcol, int Nn)
{
    uint32_t ad = as_u + buf * (STAGE_FLOATS * 4);
    const float* ap = aptr + kt;
#pragma unroll
    for (int i = 0; i < 4; i++) cp16(ad + i * 16, ap + i * 4, a_sz);
    uint32_t bd = bs_u + buf * (STAGE_FLOATS * 4);
    const float* bp = B + (size_t)(kt + brow) * Nn + colBase + bcol;
#pragma unroll
    for (int i = 0; i < 4; i++) {
        int gcol = colBase + bcol + i * 4;
        cp16(bd + i * 16, bp + i * 4, (gcol < Nn) ? 16 : 0);
    }
}

__global__ __launch_bounds__(256, 2) void gemm_tc_kernel(
    const float* __restrict__ A, const float* __restrict__ B,
    const float* __restrict__ bias, float* __restrict__ C,
    int M, int Nn, int K, int relu, int round_out)
{
    extern __shared__ float sm[];   // 3 stages of [A(128x36) | B(32x136)]

    int tid  = threadIdx.x;
    int warp = tid >> 5;
    int lane = tid & 31;
    int gid  = lane >> 2;
    int tg   = lane & 3;

    int warpM = (warp & 1) * 64;   // 2 warps over M
    int warpN = (warp >> 1) * 32;  // 4 warps over N

    int rowBase = blockIdx.y * BMt;
    int colBase = blockIdx.x * BNt;

    float acc[4][4][4];
#pragma unroll
    for (int i = 0; i < 4; i++)
#pragma unroll
        for (int j = 0; j < 4; j++)
#pragma unroll
            for (int r = 0; r < 4; r++) acc[i][j][r] = 0.f;

    // loader indices
    int arow = tid >> 1;                 // 0..127
    int acol = (tid & 1) * 16;           // 0 or 16
    int brow = tid >> 3;                 // 0..31
    int bcol = (tid & 7) * 16;           // 0..112
    int agrow = rowBase + arow;
    const float* aptr = A + (size_t)agrow * K + acol;
    int a_sz = (agrow < M) ? 16 : 0;

    uint32_t smem_u = (uint32_t)__cvta_generic_to_shared(sm);
    uint32_t as_u = smem_u + (arow * AS_STRIDE + acol) * 4;
    uint32_t bs_u = smem_u + (AS_SIZE + brow * BS_STRIDE + bcol) * 4;

    int nTiles = K / BKt;
    load_tiles(as_u, bs_u, aptr, B, 0, 0, a_sz, brow, colBase, bcol, Nn);
    cp_commit();
    if (nTiles > 1) {
        load_tiles(as_u, bs_u, aptr, B, BKt, 1, a_sz, brow, colBase, bcol, Nn);
        cp_commit();
    }

    int buf = 0;
    for (int t = 0; t < nTiles; t++) {
        if (t + 1 < nTiles) {
            asm volatile("cp.async.wait_group 1;\n" ::: "memory");
        } else {
            asm volatile("cp.async.wait_group 0;\n" ::: "memory");
        }
        __syncthreads();

        if (t + 2 < nTiles) {
            int nbuf = buf + 2; if (nbuf >= 3) nbuf -= 3;
            load_tiles(as_u, bs_u, aptr, B, (t + 2) * BKt, nbuf, a_sz, brow, colBase, bcol, Nn);
            cp_commit();
        }

        const float* Ab = sm + buf * STAGE_FLOATS;
        const float* Bb = Ab + AS_SIZE;
#pragma unroll
        for (int ks = 0; ks < 4; ks++) {
            int k0 = ks * 8;
            unsigned af[4][4], bf[4][2];
#pragma unroll
            for (int mt = 0; mt < 4; mt++) {
                int r = warpM + mt * 16;
                af[mt][0] = __float_as_uint(Ab[(r + gid) * AS_STRIDE + k0 + tg]);
                af[mt][1] = __float_as_uint(Ab[(r + gid + 8) * AS_STRIDE + k0 + tg]);
                af[mt][2] = __float_as_uint(Ab[(r + gid) * AS_STRIDE + k0 + tg + 4]);
                af[mt][3] = __float_as_uint(Ab[(r + gid + 8) * AS_STRIDE + k0 + tg + 4]);
            }
#pragma unroll
            for (int nt = 0; nt < 4; nt++) {
                int c = warpN + nt * 8;
                bf[nt][0] = __float_as_uint(Bb[(k0 + tg) * BS_STRIDE + c + gid]);
                bf[nt][1] = __float_as_uint(Bb[(k0 + tg + 4) * BS_STRIDE + c + gid]);
            }
#pragma unroll
            for (int mt = 0; mt < 4; mt++)
#pragma unroll
                for (int nt = 0; nt < 4; nt++) {
                    asm volatile(
                        "mma.sync.aligned.m16n8k8.row.col.f32.tf32.tf32.f32 "
                        "{%0,%1,%2,%3}, {%4,%5,%6,%7}, {%8,%9}, {%0,%1,%2,%3};"
                        : "+f"(acc[mt][nt][0]), "+f"(acc[mt][nt][1]),
                          "+f"(acc[mt][nt][2]), "+f"(acc[mt][nt][3])
                        : "r"(af[mt][0]), "r"(af[mt][1]), "r"(af[mt][2]), "r"(af[mt][3]),
                          "r"(bf[nt][0]), "r"(bf[nt][1]));
                }
        }
        buf++; if (buf >= 3) buf -= 3;
    }

    // epilogue
#pragma unroll
    for (int mt = 0; mt < 4; mt++) {
#pragma unroll
        for (int nt = 0; nt < 4; nt++) {
            int r0 = rowBase + warpM + mt * 16 + gid;
            int c0 = colBase + warpN + nt * 8 + tg * 2;
#pragma unroll
            for (int half = 0; half < 2; half++) {
                int row = r0 + half * 8;
                if (row < M) {
#pragma unroll
                    for (int j = 0; j < 2; j++) {
                        int col = c0 + j;
                        if (col < Nn) {
                            float v = acc[mt][nt][half * 2 + j] + bias[col];
                            if (relu) v = fmaxf(v, 0.f);
                            if (round_out) v = rna_tf32(v);
                            C[(size_t)row * Nn + col] = v;
                        }
                    }
                }
            }
        }
    }
}

// ---------------- GATv2 aggregation: one block / node, one warp / head --------
__global__ __launch_bounds__(128) void gat_kernel(
    const float* __restrict__ xlr,        // [N][1024] xl|xr
    const float* __restrict__ edge_attr,  // [E][16]
    const float* __restrict__ We,         // [16][512]
    const float* __restrict__ att,        // [512]
    const float* __restrict__ bias,       // [512]
    float* __restrict__ out)              // [N][512] (tf32-rounded: feeds GEMMs only)
{
    __shared__ float We_sh[EDGE_D * HC];
    for (int i = threadIdx.x; i < EDGE_D * HC; i += 128) We_sh[i] = We[i];
    __syncthreads();

    int w = threadIdx.x >> 5;
    int lane = threadIdx.x & 31;
    int cbase = w * EMB + lane;
    const float* Wp = We_sh + cbase;

    float att0 = __ldg(&att[cbase]);
    float att1 = __ldg(&att[cbase + 32]);
    float att2 = __ldg(&att[cbase + 64]);
    float att3 = __ldg(&att[cbase + 96]);

    int n = blockIdx.x;

    const float* xrp = xlr + (size_t)n * 1024 + HC + cbase;
    float xr0 = xrp[0], xr1 = xrp[32], xr2 = xrp[64], xr3 = xrp[96];

    float m = -CUDART_INF_F, den = 0.f;
    float a0 = 0.f, a1 = 0.f, a2 = 0.f, a3 = 0.f;

    int beg = g_off[n], end = g_off[n + 1];

#define LOAD_EDGE(IDX, SRC, EAV) do {                                        \
        const float* _ea;                                                    \
        if ((IDX) < end) {                                                   \
            SRC = __ldg(&g_csr_src[IDX]);                                    \
            _ea = edge_attr + (size_t)__ldg(&g_csr_eid[IDX]) * EDGE_D;       \
        } else {                                                             \
            SRC = n;                                                         \
            _ea = g_loop + (size_t)n * EDGE_D;                               \
        }                                                                    \
        EAV = (lane < EDGE_D) ? __ldg(&_ea[lane]) : 0.f;                     \
    } while (0)

#define LOAD_X(SRC, X0, X1, X2, X3) do {                                     \
        const float* _xp = xlr + (size_t)(SRC) * 1024 + cbase;               \
        X0 = __ldg(&_xp[0]);  X1 = __ldg(&_xp[32]);                          \
        X2 = __ldg(&_xp[64]); X3 = __ldg(&_xp[96]);                          \
    } while (0)

    int src; float eav;
    float x0, x1, x2, x3;
    LOAD_EDGE(beg, src, eav);
    LOAD_X(src, x0, x1, x2, x3);

    for (int idx = beg; idx <= end; idx++) {
        float cx0 = x0, cx1 = x1, cx2 = x2, cx3 = x3;
        float ce = eav;

        if (idx < end) {                    // prefetch next edge
            LOAD_EDGE(idx + 1, src, eav);
            LOAD_X(src, x0, x1, x2, x3);
        }

        float e0 = xr0, e1 = xr1, e2 = xr2, e3 = xr3;
#pragma unroll
        for (int d = 0; d < EDGE_D; d++) {
            float av = __shfl_sync(0xffffffffu, ce, d);
            e0 = fmaf(av, Wp[d * HC], e0);
            e1 = fmaf(av, Wp[d * HC + 32], e1);
            e2 = fmaf(av, Wp[d * HC + 64], e2);
            e3 = fmaf(av, Wp[d * HC + 96], e3);
        }
        float s0 = cx0 + e0, s1 = cx1 + e1, s2 = cx2 + e2, s3 = cx3 + e3;
        float l0 = fmaxf(s0, NEG_SLOPE * s0);
        float l1 = fmaxf(s1, NEG_SLOPE * s1);
        float l2 = fmaxf(s2, NEG_SLOPE * s2);
        float l3 = fmaxf(s3, NEG_SLOPE * s3);

        float p = l0 * att0;
        p = fmaf(l1, att1, p);
        p = fmaf(l2, att2, p);
        p = fmaf(l3, att3, p);
#pragma unroll
        for (int o = 16; o > 0; o >>= 1) p += __shfl_xor_sync(0xffffffffu, p, o);

        float nm = fmaxf(m, p);
        float corr = __expf(m - nm);
        float pe   = __expf(p - nm);
        den = den * corr + pe;
        a0 = a0 * corr + pe * cx0;
        a1 = a1 * corr + pe * cx1;
        a2 = a2 * corr + pe * cx2;
        a3 = a3 * corr + pe * cx3;
        m = nm;
    }
    float inv = 1.f / (den + 1e-16f);
    float* op = out + (size_t)n * HC + cbase;
    op[0]  = rna_tf32(fmaf(a0, inv, __ldg(&bias[cbase])));
    op[32] = rna_tf32(fmaf(a1, inv, __ldg(&bias[cbase + 32])));
    op[64] = rna_tf32(fmaf(a2, inv, __ldg(&bias[cbase + 64])));
    op[96] = rna_tf32(fmaf(a3, inv, __ldg(&bias[cbase + 96])));
#undef LOAD_EDGE
#undef LOAD_X
}

// ---------------- launch ------------------------------------------------------
extern "C" void kernel_launch(void* const* d_in, const int* in_sizes, int n_in,
                              void* d_out, int out_size) {
    const float* x     = (const float*)d_in[0];
    const void*  eidx  = d_in[1];
    const float* eattr = (const float*)d_in[2];
    const float* Wl1   = (const float*)d_in[3];
    const float* bl1   = (const float*)d_in[4];
    const float* Wr1   = (const float*)d_in[5];
    const float* br1   = (const float*)d_in[6];
    const float* We1   = (const float*)d_in[7];
    const float* att1  = (const float*)d_in[8];
    const float* bias1 = (const float*)d_in[9];
    const float* Wl2   = (const float*)d_in[10];
    const float* bl2   = (const float*)d_in[11];
    const float* Wr2   = (const float*)d_in[12];
    const float* br2   = (const float*)d_in[13];
    const float* We2   = (const float*)d_in[14];
    const float* att2  = (const float*)d_in[15];
    const float* bias2 = (const float*)d_in[16];
    const float* Wd1   = (const float*)d_in[17];
    const float* bd1   = (const float*)d_in[18];
    const float* Wd2   = (const float*)d_in[19];
    const float* bd2   = (const float*)d_in[20];
    float* out = (float*)d_out;

    float* xlr; cudaGetSymbolAddress((void**)&xlr, g_xlr);
    float* h;   cudaGetSymbolAddress((void**)&h, g_h);
    float* xA;  cudaGetSymbolAddress((void**)&xA, g_xA);
    float* Wp;  cudaGetSymbolAddress((void**)&Wp, g_Wp);
    float* bp;  cudaGetSymbolAddress((void**)&bp, g_bp);

    cudaFuncSetAttribute(gemm_tc_kernel,
                         cudaFuncAttributeMaxDynamicSharedMemorySize, GEMM_SMEM);

    dim3 blk(256);
    dim3 grid_lr(1024 / BNt, (NN + BMt - 1) / BMt);
    dim3 grid_d1((HIDDEN + BNt - 1) / BNt, (NN + BMt - 1) / BMt);
    dim3 grid_d2((OUTD + BNt - 1) / BNt, (NN + BMt - 1) / BMt);

    // ---- layer-1 GEMM first (4th launch -> ncu capture lands here) ----
    init_kernel<<<(NN + 255) / 256, 256>>>(eidx);
    round_x_kernel<<<(NN * NODE_D + 255) / 256, 256>>>(x);
    pack_kernel<<<(NODE_D * 1024 + 255) / 256, 256>>>(Wl1, Wr1, bl1, br1, HC, 1024, NODE_D);
    gemm_tc_kernel<<<grid_lr, blk, GEMM_SMEM>>>(xA, Wp, bp, xlr, NN, 1024, NODE_D, 0, 0);

    // ---- CSR preprocessing ----
    count_kernel<<<(EE + 255) / 256, 256>>>(eidx);
    scan_kernel<<<1, 1024>>>();
    scatter_kernel<<<(EE + 255) / 256, 256>>>(eidx);
    loopattr_kernel<<<(NN + 3) / 4, 128>>>(eattr);

    // ---- layer 1 aggregation ----
    gat_kernel<<<NN, 128>>>(xlr, eattr, We1, att1, bias1, h);

    // ---- layer 2 ----
    pack_kernel<<<(HC * 1024 + 255) / 256, 256>>>(Wl2, Wr2, bl2, br2, HC, 1024, HC);
    gemm_tc_kernel<<<grid_lr, blk, GEMM_SMEM>>>(h, Wp, bp, xlr, NN, 1024, HC, 0, 0);
    gat_kernel<<<NN, 128>>>(xlr, eattr, We2, att2, bias2, h);

    // ---- decoder ----
    float* hid = xlr;  // reuse scratch
    pack_kernel<<<(HC * HIDDEN + 255) / 256, 256>>>(Wd1, Wd1, bd1, bd1, HIDDEN, HIDDEN, HC);
    gemm_tc_kernel<<<grid_d1, blk, GEMM_SMEM>>>(h, Wp, bp, hid, NN, HIDDEN, HC, 1, 1);
    pack_kernel<<<(HIDDEN * OUTD + 255) / 256, 256>>>(Wd2, Wd2, bd2, bd2, OUTD, OUTD, HIDDEN);
    gemm_tc_kernel<<<grid_d2, blk, GEMM_SMEM>>>(hid, Wp, bp, out, NN, OUTD, HIDDEN, 0, 0);
}